// round 11
// baseline (speedup 1.0000x reference)
#include <cuda_runtime.h>
#include <cuda_bf16.h>
#include <cstdint>

#define NB 512
#define ND 512
#define MARGIN 0.2f
#define INF_F 1e30f
#define NSPLIT 16       // K splits of 32
#define KB 32           // K per block

typedef unsigned long long ull;

// ---------------- scratch ----------------
__device__ float g_P[NSPLIT][NB * NB];   // split-K partial dot products (16 MB)
__device__ float g_diag[NSPLIT][NB];     // per-split diagonal (32 KB)

struct Ctl {
    unsigned long long acc;   // fixed-point loss sum (x 2^32)
    unsigned long long cnt;   // valid pair count
    int done;
    int pad;
};
__device__ Ctl g_ctl;

// ---------------- f32x2 helpers ----------------
__device__ __forceinline__ ull dup2(float x) {
    ull r;
    asm("mov.b64 %0, {%1, %1};" : "=l"(r) : "r"(__float_as_uint(x)));
    return r;
}
__device__ __forceinline__ void fma2(ull& d, ull a, ull b) {
    asm("fma.rn.f32x2 %0, %1, %2, %0;" : "+l"(d) : "l"(a), "l"(b));
}
__device__ __forceinline__ void unpk(ull v, float& lo, float& hi) {
    unsigned l, h;
    asm("mov.b64 {%0, %1}, %2;" : "=r"(l), "=r"(h) : "l"(v));
    lo = __uint_as_float(l);
    hi = __uint_as_float(h);
}

// =====================================================================
// Kernel A: GEMM. grid (4,4,16), 256 threads, 2 blocks/SM, 32KB smem.
//   R10-validated layout: A,B plain f32 [k][128]; per kk 2x LDS.128
//   each (A broadcast, B 16B/lane). Diagonal blocks also extract the
//   per-split diagonal into g_diag[bz].
// =====================================================================
__global__ void __launch_bounds__(256, 2)
k_gemm(const float* __restrict__ E) {
    __shared__ float As[KB][128];   // 16 KB
    __shared__ float Bs[KB][128];   // 16 KB

    const int tid = threadIdx.x;
    const int bj = blockIdx.x, bi = blockIdx.y, bz = blockIdx.z;
    const int lane = tid & 31, warp = tid >> 5;

    // ---------- stage tiles (transposed, conflict-free stores) ----------
    {
        const int r = tid & 127;
        const int half = tid >> 7;              // 0/1 -> k halves of 16
        const float* Ag = E + (size_t)(bi * 128 + r) * ND + bz * KB + half * 16;
        const float* Bg = E + (size_t)(bj * 128 + r) * ND + bz * KB + half * 16;
#pragma unroll
        for (int i = 0; i < 4; i++) {
            const int k = half * 16 + i * 4;
            float4 va = *reinterpret_cast<const float4*>(Ag + i * 4);
            float4 vb = *reinterpret_cast<const float4*>(Bg + i * 4);
            As[k + 0][r] = va.x; As[k + 1][r] = va.y;
            As[k + 2][r] = va.z; As[k + 3][r] = va.w;
            Bs[k + 0][r] = vb.x; Bs[k + 1][r] = vb.y;
            Bs[k + 2][r] = vb.z; Bs[k + 3][r] = vb.w;
        }
    }
    __syncthreads();

    // ---------- compute: 8x8 per thread ----------
    const int wr = warp >> 1, wc = warp & 1;
    const int ly = lane >> 3, lx = lane & 7;
    const int rbase = wr * 32 + ly * 8;
    const int cbase = wc * 64 + lx * 4;

    ull acc[4][8];
#pragma unroll
    for (int i = 0; i < 4; i++)
#pragma unroll
        for (int j = 0; j < 8; j++) acc[i][j] = 0ull;

#pragma unroll 4
    for (int kk = 0; kk < KB; kk++) {
        ulonglong2 A01 = *reinterpret_cast<const ulonglong2*>(&As[kk][rbase + 0]);
        ulonglong2 A23 = *reinterpret_cast<const ulonglong2*>(&As[kk][rbase + 4]);
        float4 bv0 = *reinterpret_cast<const float4*>(&Bs[kk][cbase]);
        float4 bv1 = *reinterpret_cast<const float4*>(&Bs[kk][cbase + 32]);
        ull b0 = dup2(bv0.x), b1 = dup2(bv0.y), b2 = dup2(bv0.z), b3 = dup2(bv0.w);
        ull b4 = dup2(bv1.x), b5 = dup2(bv1.y), b6 = dup2(bv1.z), b7 = dup2(bv1.w);
        fma2(acc[0][0], A01.x, b0); fma2(acc[1][0], A01.y, b0);
        fma2(acc[2][0], A23.x, b0); fma2(acc[3][0], A23.y, b0);
        fma2(acc[0][1], A01.x, b1); fma2(acc[1][1], A01.y, b1);
        fma2(acc[2][1], A23.x, b1); fma2(acc[3][1], A23.y, b1);
        fma2(acc[0][2], A01.x, b2); fma2(acc[1][2], A01.y, b2);
        fma2(acc[2][2], A23.x, b2); fma2(acc[3][2], A23.y, b2);
        fma2(acc[0][3], A01.x, b3); fma2(acc[1][3], A01.y, b3);
        fma2(acc[2][3], A23.x, b3); fma2(acc[3][3], A23.y, b3);
        fma2(acc[0][4], A01.x, b4); fma2(acc[1][4], A01.y, b4);
        fma2(acc[2][4], A23.x, b4); fma2(acc[3][4], A23.y, b4);
        fma2(acc[0][5], A01.x, b5); fma2(acc[1][5], A01.y, b5);
        fma2(acc[2][5], A23.x, b5); fma2(acc[3][5], A23.y, b5);
        fma2(acc[0][6], A01.x, b6); fma2(acc[1][6], A01.y, b6);
        fma2(acc[2][6], A23.x, b6); fma2(acc[3][6], A23.y, b6);
        fma2(acc[0][7], A01.x, b7); fma2(acc[1][7], A01.y, b7);
        fma2(acc[2][7], A23.x, b7); fma2(acc[3][7], A23.y, b7);
    }

    // ---------- epilogue ----------
    {
        float* dst = g_P[bz];
        const int c0 = bj * 128 + cbase;
#pragma unroll
        for (int rp = 0; rp < 4; rp++) {
            float lo[8], hi[8];
#pragma unroll
            for (int j = 0; j < 8; j++) unpk(acc[rp][j], lo[j], hi[j]);
            const int r0 = bi * 128 + rbase + 2 * rp;
            float* d0 = &dst[(size_t)r0 * NB + c0];
            float* d1 = &dst[(size_t)(r0 + 1) * NB + c0];
            *reinterpret_cast<float4*>(d0)      = make_float4(lo[0], lo[1], lo[2], lo[3]);
            *reinterpret_cast<float4*>(d0 + 32) = make_float4(lo[4], lo[5], lo[6], lo[7]);
            *reinterpret_cast<float4*>(d1)      = make_float4(hi[0], hi[1], hi[2], hi[3]);
            *reinterpret_cast<float4*>(d1 + 32) = make_float4(hi[4], hi[5], hi[6], hi[7]);
        }
    }

    // ---------- diagonal extraction (block-local; __syncthreads orders
    //            the block's own global stores before these loads) ----------
    if (bi == bj) {
        __syncthreads();
        if (tid < 128) {
            const int r = bi * 128 + tid;
            g_diag[bz][r] = g_P[bz][(size_t)r * NB + r];
        }
    }
}

// =====================================================================
// Kernel B: block-per-anchor mining. grid 512 x 128.
//   sq from g_diag (contiguous, fixed z-order). Row fold across splits.
// =====================================================================
__global__ void __launch_bounds__(128, 8)
k_mine(const int* __restrict__ labels, float* __restrict__ out) {
    __shared__ float s_sq[NB];
    __shared__ float s_d[NB];
    __shared__ int s_lab[NB];
    __shared__ float s_nm[4];
    __shared__ float s_nmin;

    const int a = blockIdx.x;
    const int tid = threadIdx.x;
    const int lane = tid & 31, warp = tid >> 5;

    // ---- stage sq (fold contiguous per-split diagonals) + labels ----
    {
        const int j0 = tid * 4;
        float4 s = make_float4(0.f, 0.f, 0.f, 0.f);
#pragma unroll
        for (int z = 0; z < NSPLIT; z++) {
            float4 v = *reinterpret_cast<const float4*>(&g_diag[z][j0]);
            s.x += v.x; s.y += v.y; s.z += v.z; s.w += v.w;
        }
        *reinterpret_cast<float4*>(&s_sq[j0]) = s;
        *reinterpret_cast<int4*>(&s_lab[j0]) =
            *reinterpret_cast<const int4*>(&labels[j0]);
    }
    __syncthreads();

    const float sqa = s_sq[a];
    const int la = s_lab[a];

    // ---- fold row a across splits; distances into smem ----
    {
        const int j0 = tid * 4;
        float4 p = make_float4(0.f, 0.f, 0.f, 0.f);
#pragma unroll
        for (int z = 0; z < NSPLIT; z++) {
            float4 v = *reinterpret_cast<const float4*>(&g_P[z][(size_t)a * NB + j0]);
            p.x += v.x; p.y += v.y; p.z += v.z; p.w += v.w;
        }
        s_d[j0 + 0] = fmaxf(sqa + s_sq[j0 + 0] - 2.f * p.x, 0.f);
        s_d[j0 + 1] = fmaxf(sqa + s_sq[j0 + 1] - 2.f * p.y, 0.f);
        s_d[j0 + 2] = fmaxf(sqa + s_sq[j0 + 2] - 2.f * p.z, 0.f);
        s_d[j0 + 3] = fmaxf(sqa + s_sq[j0 + 3] - 2.f * p.w, 0.f);
    }
    __syncthreads();

    // ---- register copies: d[t] = s_d[t*32+lane] ----
    float d[16];
    int lb[16];
#pragma unroll
    for (int t = 0; t < 16; t++) {
        d[t] = s_d[t * 32 + lane];
        lb[t] = s_lab[t * 32 + lane];
    }

    // ---- block-wide min over negatives (fmin: order-independent) ----
    {
        float nm = INF_F;
#pragma unroll
        for (int t = 0; t < 16; t++)
            if (lb[t] != la) nm = fminf(nm, d[t]);
#pragma unroll
        for (int o = 16; o > 0; o >>= 1)
            nm = fminf(nm, __shfl_xor_sync(0xFFFFFFFFu, nm, o));
        if (lane == 0) s_nm[warp] = nm;
    }
    __syncthreads();
    if (tid == 0)
        s_nmin = fminf(fminf(s_nm[0], s_nm[1]), fminf(s_nm[2], s_nm[3]));
    __syncthreads();
    const float nmin = s_nmin;

    long long accll = 0, cntll = 0;
    if (nmin < 1e29f) {
        float sum = 0.f;
        int cnt = 0;
#pragma unroll 1
        for (int tt0 = 0; tt0 < 4; tt0++) {
            const int t = warp * 4 + tt0;
            const int j = t * 32 + lane;
            unsigned m = __ballot_sync(0xFFFFFFFFu, (j > a) && (lb[t] == la));
            while (m) {
                const int lp = __ffs(m) - 1;
                m &= m - 1;
                const float ap = __shfl_sync(0xFFFFFFFFu, d[t], lp);
                const float apM = ap + MARGIN;
                float smin = INF_F;
#pragma unroll
                for (int q = 0; q < 16; q++) {
                    bool semi = (lb[q] != la) && (d[q] > ap) && (d[q] < apM);
                    if (semi) smin = fminf(smin, d[q]);
                }
#pragma unroll
                for (int o = 16; o > 0; o >>= 1)
                    smin = fminf(smin, __shfl_xor_sync(0xFFFFFFFFu, smin, o));
                const float negd = (smin < 1e29f) ? smin : nmin;
                sum += fmaxf(ap - negd + MARGIN, 0.f);
                cnt++;
            }
        }
        if (lane == 0 && cnt) {
            accll = __double2ll_rn((double)sum * 4294967296.0);
            cntll = cnt;
        }
    }
    if (lane == 0 && (accll | cntll)) {
        atomicAdd(&g_ctl.acc, (ull)accll);
        atomicAdd(&g_ctl.cnt, (ull)cntll);
    }

    // ---- finalize: last block writes the scalar ----
    __syncthreads();
    __threadfence();
    if (tid == 0) {
        const int o = atomicAdd(&g_ctl.done, 1);
        if (o == NB - 1) {
            __threadfence();
            ull av = *(volatile ull*)&g_ctl.acc;
            ull cv = *(volatile ull*)&g_ctl.cnt;
            out[0] = (float)(((double)av / 4294967296.0) / (double)(cv ? cv : 1ull));
        }
    }
}

extern "C" void kernel_launch(void* const* d_in, const int* in_sizes, int n_in,
                              void* d_out, int out_size) {
    const float* emb = (const float*)d_in[0];
    const int* labels = (const int*)d_in[1];
    float* out = (float*)d_out;

    void* ctl = nullptr;
    cudaGetSymbolAddress(&ctl, g_ctl);
    cudaMemsetAsync(ctl, 0, sizeof(Ctl));

    dim3 grid(4, 4, NSPLIT);
    k_gemm<<<grid, 256>>>(emb);
    k_mine<<<NB, 128>>>(labels, out);
}

// round 12
// speedup vs baseline: 1.0182x; 1.0182x over previous
#include <cuda_runtime.h>
#include <cuda_bf16.h>
#include <cstdint>

#define NB 512
#define ND 512
#define MARGIN 0.2f
#define INF_F 1e30f
#define NSPLIT 16       // K splits of 32
#define KB 32           // K per block

typedef unsigned long long ull;

// ---------------- scratch ----------------
__device__ float g_P[NSPLIT][NB * NB];   // split-K partial dot products (16 MB)
__device__ float g_diag[NSPLIT][NB];     // per-split diagonal (32 KB)

struct Ctl {
    unsigned long long acc;   // fixed-point loss sum (x 2^32)
    unsigned long long cnt;   // valid pair count
    int done;
    int pad;
};
__device__ Ctl g_ctl;

// ---------------- f32x2 helpers ----------------
__device__ __forceinline__ ull dup2(float x) {
    ull r;
    asm("mov.b64 %0, {%1, %1};" : "=l"(r) : "r"(__float_as_uint(x)));
    return r;
}
__device__ __forceinline__ void fma2(ull& d, ull a, ull b) {
    asm("fma.rn.f32x2 %0, %1, %2, %0;" : "+l"(d) : "l"(a), "l"(b));
}
__device__ __forceinline__ void unpk(ull v, float& lo, float& hi) {
    unsigned l, h;
    asm("mov.b64 {%0, %1}, %2;" : "=r"(l), "=r"(h) : "l"(v));
    lo = __uint_as_float(l);
    hi = __uint_as_float(h);
}

// =====================================================================
// Kernel A: GEMM. grid (4,4,16), 256 threads, 2 blocks/SM, 32KB smem.
//   (R11-validated, unchanged)
// =====================================================================
__global__ void __launch_bounds__(256, 2)
k_gemm(const float* __restrict__ E) {
    __shared__ float As[KB][128];   // 16 KB
    __shared__ float Bs[KB][128];   // 16 KB

    const int tid = threadIdx.x;
    const int bj = blockIdx.x, bi = blockIdx.y, bz = blockIdx.z;
    const int lane = tid & 31, warp = tid >> 5;

    {
        const int r = tid & 127;
        const int half = tid >> 7;
        const float* Ag = E + (size_t)(bi * 128 + r) * ND + bz * KB + half * 16;
        const float* Bg = E + (size_t)(bj * 128 + r) * ND + bz * KB + half * 16;
#pragma unroll
        for (int i = 0; i < 4; i++) {
            const int k = half * 16 + i * 4;
            float4 va = *reinterpret_cast<const float4*>(Ag + i * 4);
            float4 vb = *reinterpret_cast<const float4*>(Bg + i * 4);
            As[k + 0][r] = va.x; As[k + 1][r] = va.y;
            As[k + 2][r] = va.z; As[k + 3][r] = va.w;
            Bs[k + 0][r] = vb.x; Bs[k + 1][r] = vb.y;
            Bs[k + 2][r] = vb.z; Bs[k + 3][r] = vb.w;
        }
    }
    __syncthreads();

    const int wr = warp >> 1, wc = warp & 1;
    const int ly = lane >> 3, lx = lane & 7;
    const int rbase = wr * 32 + ly * 8;
    const int cbase = wc * 64 + lx * 4;

    ull acc[4][8];
#pragma unroll
    for (int i = 0; i < 4; i++)
#pragma unroll
        for (int j = 0; j < 8; j++) acc[i][j] = 0ull;

#pragma unroll 4
    for (int kk = 0; kk < KB; kk++) {
        ulonglong2 A01 = *reinterpret_cast<const ulonglong2*>(&As[kk][rbase + 0]);
        ulonglong2 A23 = *reinterpret_cast<const ulonglong2*>(&As[kk][rbase + 4]);
        float4 bv0 = *reinterpret_cast<const float4*>(&Bs[kk][cbase]);
        float4 bv1 = *reinterpret_cast<const float4*>(&Bs[kk][cbase + 32]);
        ull b0 = dup2(bv0.x), b1 = dup2(bv0.y), b2 = dup2(bv0.z), b3 = dup2(bv0.w);
        ull b4 = dup2(bv1.x), b5 = dup2(bv1.y), b6 = dup2(bv1.z), b7 = dup2(bv1.w);
        fma2(acc[0][0], A01.x, b0); fma2(acc[1][0], A01.y, b0);
        fma2(acc[2][0], A23.x, b0); fma2(acc[3][0], A23.y, b0);
        fma2(acc[0][1], A01.x, b1); fma2(acc[1][1], A01.y, b1);
        fma2(acc[2][1], A23.x, b1); fma2(acc[3][1], A23.y, b1);
        fma2(acc[0][2], A01.x, b2); fma2(acc[1][2], A01.y, b2);
        fma2(acc[2][2], A23.x, b2); fma2(acc[3][2], A23.y, b2);
        fma2(acc[0][3], A01.x, b3); fma2(acc[1][3], A01.y, b3);
        fma2(acc[2][3], A23.x, b3); fma2(acc[3][3], A23.y, b3);
        fma2(acc[0][4], A01.x, b4); fma2(acc[1][4], A01.y, b4);
        fma2(acc[2][4], A23.x, b4); fma2(acc[3][4], A23.y, b4);
        fma2(acc[0][5], A01.x, b5); fma2(acc[1][5], A01.y, b5);
        fma2(acc[2][5], A23.x, b5); fma2(acc[3][5], A23.y, b5);
        fma2(acc[0][6], A01.x, b6); fma2(acc[1][6], A01.y, b6);
        fma2(acc[2][6], A23.x, b6); fma2(acc[3][6], A23.y, b6);
        fma2(acc[0][7], A01.x, b7); fma2(acc[1][7], A01.y, b7);
        fma2(acc[2][7], A23.x, b7); fma2(acc[3][7], A23.y, b7);
    }

    {
        float* dst = g_P[bz];
        const int c0 = bj * 128 + cbase;
#pragma unroll
        for (int rp = 0; rp < 4; rp++) {
            float lo[8], hi[8];
#pragma unroll
            for (int j = 0; j < 8; j++) unpk(acc[rp][j], lo[j], hi[j]);
            const int r0 = bi * 128 + rbase + 2 * rp;
            float* d0 = &dst[(size_t)r0 * NB + c0];
            float* d1 = &dst[(size_t)(r0 + 1) * NB + c0];
            *reinterpret_cast<float4*>(d0)      = make_float4(lo[0], lo[1], lo[2], lo[3]);
            *reinterpret_cast<float4*>(d0 + 32) = make_float4(lo[4], lo[5], lo[6], lo[7]);
            *reinterpret_cast<float4*>(d1)      = make_float4(hi[0], hi[1], hi[2], hi[3]);
            *reinterpret_cast<float4*>(d1 + 32) = make_float4(hi[4], hi[5], hi[6], hi[7]);
        }
    }

    // diagonal extraction (block-local)
    if (bi == bj) {
        __syncthreads();
        if (tid < 128) {
            const int r = bi * 128 + tid;
            g_diag[bz][r] = g_P[bz][(size_t)r * NB + r];
        }
    }
}

// =====================================================================
// Kernel B: block-per-anchor mining. grid 512 x 128.
//   launch_bounds(128,4): 128-reg budget so the 16-split folds keep
//   full MLP (load-all-then-sum).
// =====================================================================
__global__ void __launch_bounds__(128, 4)
k_mine(const int* __restrict__ labels, float* __restrict__ out) {
    __shared__ float s_sq[NB];
    __shared__ float s_d[NB];
    __shared__ int s_lab[NB];
    __shared__ float s_nm[4];
    __shared__ float s_nmin;

    const int a = blockIdx.x;
    const int tid = threadIdx.x;
    const int lane = tid & 31, warp = tid >> 5;
    const int j0 = tid * 4;

    // ---- stage sq (16-way fold, full MLP) + labels ----
    {
        float4 v[NSPLIT];
#pragma unroll
        for (int z = 0; z < NSPLIT; z++)
            v[z] = *reinterpret_cast<const float4*>(&g_diag[z][j0]);
        float4 s = make_float4(0.f, 0.f, 0.f, 0.f);
#pragma unroll
        for (int z = 0; z < NSPLIT; z++) {
            s.x += v[z].x; s.y += v[z].y; s.z += v[z].z; s.w += v[z].w;
        }
        *reinterpret_cast<float4*>(&s_sq[j0]) = s;
        *reinterpret_cast<int4*>(&s_lab[j0]) =
            *reinterpret_cast<const int4*>(&labels[j0]);
    }
    __syncthreads();

    const float sqa = s_sq[a];
    const int la = s_lab[a];

    // ---- fold row a across splits (full MLP); distances into smem ----
    {
        float4 v[NSPLIT];
#pragma unroll
        for (int z = 0; z < NSPLIT; z++)
            v[z] = *reinterpret_cast<const float4*>(&g_P[z][(size_t)a * NB + j0]);
        float4 p = make_float4(0.f, 0.f, 0.f, 0.f);
#pragma unroll
        for (int z = 0; z < NSPLIT; z++) {
            p.x += v[z].x; p.y += v[z].y; p.z += v[z].z; p.w += v[z].w;
        }
        s_d[j0 + 0] = fmaxf(sqa + s_sq[j0 + 0] - 2.f * p.x, 0.f);
        s_d[j0 + 1] = fmaxf(sqa + s_sq[j0 + 1] - 2.f * p.y, 0.f);
        s_d[j0 + 2] = fmaxf(sqa + s_sq[j0 + 2] - 2.f * p.z, 0.f);
        s_d[j0 + 3] = fmaxf(sqa + s_sq[j0 + 3] - 2.f * p.w, 0.f);
    }
    __syncthreads();

    // ---- register copies: d[t] = s_d[t*32+lane] ----
    float d[16];
    int lb[16];
#pragma unroll
    for (int t = 0; t < 16; t++) {
        d[t] = s_d[t * 32 + lane];
        lb[t] = s_lab[t * 32 + lane];
    }

    // ---- block-wide min over negatives ----
    {
        float nm = INF_F;
#pragma unroll
        for (int t = 0; t < 16; t++)
            if (lb[t] != la) nm = fminf(nm, d[t]);
#pragma unroll
        for (int o = 16; o > 0; o >>= 1)
            nm = fminf(nm, __shfl_xor_sync(0xFFFFFFFFu, nm, o));
        if (lane == 0) s_nm[warp] = nm;
    }
    __syncthreads();
    if (tid == 0)
        s_nmin = fminf(fminf(s_nm[0], s_nm[1]), fminf(s_nm[2], s_nm[3]));
    __syncthreads();
    const float nmin = s_nmin;

    long long accll = 0, cntll = 0;
    if (nmin < 1e29f) {
        float sum = 0.f;
        int cnt = 0;
#pragma unroll 1
        for (int tt0 = 0; tt0 < 4; tt0++) {
            const int t = warp * 4 + tt0;
            const int j = t * 32 + lane;
            unsigned m = __ballot_sync(0xFFFFFFFFu, (j > a) && (lb[t] == la));
            while (m) {
                const int lp = __ffs(m) - 1;
                m &= m - 1;
                const float ap = __shfl_sync(0xFFFFFFFFu, d[t], lp);
                const float apM = ap + MARGIN;
                float smin = INF_F;
#pragma unroll
                for (int q = 0; q < 16; q++) {
                    bool semi = (lb[q] != la) && (d[q] > ap) && (d[q] < apM);
                    if (semi) smin = fminf(smin, d[q]);
                }
#pragma unroll
                for (int o = 16; o > 0; o >>= 1)
                    smin = fminf(smin, __shfl_xor_sync(0xFFFFFFFFu, smin, o));
                const float negd = (smin < 1e29f) ? smin : nmin;
                sum += fmaxf(ap - negd + MARGIN, 0.f);
                cnt++;
            }
        }
        if (lane == 0 && cnt) {
            accll = __double2ll_rn((double)sum * 4294967296.0);
            cntll = cnt;
        }
    }
    if (lane == 0 && (accll | cntll)) {
        atomicAdd(&g_ctl.acc, (ull)accll);
        atomicAdd(&g_ctl.cnt, (ull)cntll);
    }

    // ---- finalize ----
    __syncthreads();
    __threadfence();
    if (tid == 0) {
        const int o = atomicAdd(&g_ctl.done, 1);
        if (o == NB - 1) {
            __threadfence();
            ull av = *(volatile ull*)&g_ctl.acc;
            ull cv = *(volatile ull*)&g_ctl.cnt;
            out[0] = (float)(((double)av / 4294967296.0) / (double)(cv ? cv : 1ull));
        }
    }
}

extern "C" void kernel_launch(void* const* d_in, const int* in_sizes, int n_in,
                              void* d_out, int out_size) {
    const float* emb = (const float*)d_in[0];
    const int* labels = (const int*)d_in[1];
    float* out = (float*)d_out;

    void* ctl = nullptr;
    cudaGetSymbolAddress(&ctl, g_ctl);
    cudaMemsetAsync(ctl, 0, sizeof(Ctl));

    dim3 grid(4, 4, NSPLIT);
    k_gemm<<<grid, 256>>>(emb);
    k_mine<<<NB, 128>>>(labels, out);
}

// round 13
// speedup vs baseline: 1.1106x; 1.0908x over previous
#include <cuda_runtime.h>
#include <cuda_bf16.h>
#include <cstdint>

#define NB 512
#define ND 512
#define MARGIN 0.2f
#define INF_F 1e30f
#define NSPLIT 8        // K splits of 64
#define KB 64           // K per block

typedef unsigned long long ull;

// ---------------- scratch ----------------
__device__ float g_P[NSPLIT][NB * NB];   // split-K partial dot products (8 MB)
__device__ float g_diag[NSPLIT][NB];     // per-split diagonal (16 KB)

struct Ctl {
    unsigned long long acc;   // fixed-point loss sum (x 2^32)
    unsigned long long cnt;   // valid pair count
    int done;
    int pad;
};
__device__ Ctl g_ctl;

// ---------------- f32x2 helpers ----------------
__device__ __forceinline__ ull dup2(float x) {
    ull r;
    asm("mov.b64 %0, {%1, %1};" : "=l"(r) : "r"(__float_as_uint(x)));
    return r;
}
__device__ __forceinline__ void fma2(ull& d, ull a, ull b) {
    asm("fma.rn.f32x2 %0, %1, %2, %0;" : "+l"(d) : "l"(a), "l"(b));
}
__device__ __forceinline__ void unpk(ull v, float& lo, float& hi) {
    unsigned l, h;
    asm("mov.b64 {%0, %1}, %2;" : "=r"(l), "=r"(h) : "l"(v));
    lo = __uint_as_float(l);
    hi = __uint_as_float(h);
}

// =====================================================================
// Kernel A: GEMM 128x64x64 tiles. grid (bj=8, bi=4, bz=8) = 256 blocks,
//   256 threads, 2 blocks/SM, 48KB static smem.
//   Warp w: wr=w>>1 (4 row warps of 32), wc=w&1 (2 col warps of 32).
//   Lane: ly=lane>>3 (rows wr*32+ly*8..+7), lx=lane&7 (cols wc*32+lx*4).
//   Block (0,0,0) zeroes g_ctl (mine runs strictly after -> safe).
// =====================================================================
__global__ void __launch_bounds__(256, 2)
k_gemm(const float* __restrict__ E) {
    __shared__ float As[KB][128];   // 32 KB [k][row]  (M=128)
    __shared__ float Bs[KB][64];    // 16 KB [k][col]  (N=64)

    const int tid = threadIdx.x;
    const int bj = blockIdx.x, bi = blockIdx.y, bz = blockIdx.z;
    const int lane = tid & 31, warp = tid >> 5;

    if ((bi | bj | bz) == 0 && tid == 0) {
        g_ctl.acc = 0ull; g_ctl.cnt = 0ull; g_ctl.done = 0;
    }

    // ---------- stage tiles (transposed, conflict-free stores) ----------
    {
        // A: 128 rows x 64 k = 2048 float4 -> 8 per thread
        const int r = tid & 127;
        const int half = tid >> 7;              // k half of 32
        const float* Ag = E + (size_t)(bi * 128 + r) * ND + bz * KB + half * 32;
#pragma unroll
        for (int i = 0; i < 8; i++) {
            const int k = half * 32 + i * 4;
            float4 va = *reinterpret_cast<const float4*>(Ag + i * 4);
            As[k + 0][r] = va.x; As[k + 1][r] = va.y;
            As[k + 2][r] = va.z; As[k + 3][r] = va.w;
        }
        // B: 64 rows x 64 k = 1024 float4 -> 4 per thread
        const int rb = tid & 63;
        const int kq = tid >> 6;                // k quarter of 16
        const float* Bg = E + (size_t)(bj * 64 + rb) * ND + bz * KB + kq * 16;
#pragma unroll
        for (int i = 0; i < 4; i++) {
            const int k = kq * 16 + i * 4;
            float4 vb = *reinterpret_cast<const float4*>(Bg + i * 4);
            Bs[k + 0][rb] = vb.x; Bs[k + 1][rb] = vb.y;
            Bs[k + 2][rb] = vb.z; Bs[k + 3][rb] = vb.w;
        }
    }
    __syncthreads();

    // ---------- compute: 8 rows x 4 cols per thread ----------
    const int wr = warp >> 1;          // 0..3
    const int wc = warp & 1;           // 0..1
    const int ly = lane >> 3, lx = lane & 7;
    const int rbase = wr * 32 + ly * 8;
    const int cb = wc * 32 + lx * 4;

    ull acc[4][4];
#pragma unroll
    for (int i = 0; i < 4; i++)
#pragma unroll
        for (int j = 0; j < 4; j++) acc[i][j] = 0ull;

#pragma unroll 4
    for (int kk = 0; kk < KB; kk++) {
        ulonglong2 A01 = *reinterpret_cast<const ulonglong2*>(&As[kk][rbase + 0]);
        ulonglong2 A23 = *reinterpret_cast<const ulonglong2*>(&As[kk][rbase + 4]);
        float4 bv = *reinterpret_cast<const float4*>(&Bs[kk][cb]);
        ull b0 = dup2(bv.x), b1 = dup2(bv.y), b2 = dup2(bv.z), b3 = dup2(bv.w);
        fma2(acc[0][0], A01.x, b0); fma2(acc[1][0], A01.y, b0);
        fma2(acc[2][0], A23.x, b0); fma2(acc[3][0], A23.y, b0);
        fma2(acc[0][1], A01.x, b1); fma2(acc[1][1], A01.y, b1);
        fma2(acc[2][1], A23.x, b1); fma2(acc[3][1], A23.y, b1);
        fma2(acc[0][2], A01.x, b2); fma2(acc[1][2], A01.y, b2);
        fma2(acc[2][2], A23.x, b2); fma2(acc[3][2], A23.y, b2);
        fma2(acc[0][3], A01.x, b3); fma2(acc[1][3], A01.y, b3);
        fma2(acc[2][3], A23.x, b3); fma2(acc[3][3], A23.y, b3);
    }

    // ---------- epilogue ----------
    {
        float* dst = g_P[bz];
        const int c0 = bj * 64 + cb;
#pragma unroll
        for (int rp = 0; rp < 4; rp++) {
            float lo[4], hi[4];
#pragma unroll
            for (int j = 0; j < 4; j++) unpk(acc[rp][j], lo[j], hi[j]);
            const int r0 = bi * 128 + rbase + 2 * rp;
            *reinterpret_cast<float4*>(&dst[(size_t)r0 * NB + c0]) =
                make_float4(lo[0], lo[1], lo[2], lo[3]);
            *reinterpret_cast<float4*>(&dst[(size_t)(r0 + 1) * NB + c0]) =
                make_float4(hi[0], hi[1], hi[2], hi[3]);
        }
    }

    // ---------- diagonal extraction (cols bj*64..+63 inside rows?) ----------
    if ((bj >> 1) == bi) {
        __syncthreads();           // block's own STGs visible to its loads
        if (tid < 64) {
            const int r = bj * 64 + tid;
            g_diag[bz][r] = g_P[bz][(size_t)r * NB + r];
        }
    }
}

// =====================================================================
// Kernel B: block-per-anchor mining. grid 512 x 128.
//   Fold: 8 named independent LDG.128 (force MLP).
// =====================================================================
__global__ void __launch_bounds__(128, 4)
k_mine(const int* __restrict__ labels, float* __restrict__ out) {
    __shared__ float s_sq[NB];
    __shared__ float s_d[NB];
    __shared__ int s_lab[NB];
    __shared__ float s_nm[4];
    __shared__ float s_nmin;

    const int a = blockIdx.x;
    const int tid = threadIdx.x;
    const int lane = tid & 31, warp = tid >> 5;
    const int j0 = tid * 4;

    // ---- stage sq (8-way fold of contiguous diagonals) + labels ----
    {
        float4 u0 = *reinterpret_cast<const float4*>(&g_diag[0][j0]);
        float4 u1 = *reinterpret_cast<const float4*>(&g_diag[1][j0]);
        float4 u2 = *reinterpret_cast<const float4*>(&g_diag[2][j0]);
        float4 u3 = *reinterpret_cast<const float4*>(&g_diag[3][j0]);
        float4 u4 = *reinterpret_cast<const float4*>(&g_diag[4][j0]);
        float4 u5 = *reinterpret_cast<const float4*>(&g_diag[5][j0]);
        float4 u6 = *reinterpret_cast<const float4*>(&g_diag[6][j0]);
        float4 u7 = *reinterpret_cast<const float4*>(&g_diag[7][j0]);
        float4 s;
        s.x = ((u0.x + u1.x) + (u2.x + u3.x)) + ((u4.x + u5.x) + (u6.x + u7.x));
        s.y = ((u0.y + u1.y) + (u2.y + u3.y)) + ((u4.y + u5.y) + (u6.y + u7.y));
        s.z = ((u0.z + u1.z) + (u2.z + u3.z)) + ((u4.z + u5.z) + (u6.z + u7.z));
        s.w = ((u0.w + u1.w) + (u2.w + u3.w)) + ((u4.w + u5.w) + (u6.w + u7.w));
        *reinterpret_cast<float4*>(&s_sq[j0]) = s;
        *reinterpret_cast<int4*>(&s_lab[j0]) =
            *reinterpret_cast<const int4*>(&labels[j0]);
    }
    __syncthreads();

    const float sqa = s_sq[a];
    const int la = s_lab[a];

    // ---- fold row a across 8 splits (named loads -> full MLP) ----
    {
        const size_t off = (size_t)a * NB + j0;
        float4 v0 = *reinterpret_cast<const float4*>(&g_P[0][off]);
        float4 v1 = *reinterpret_cast<const float4*>(&g_P[1][off]);
        float4 v2 = *reinterpret_cast<const float4*>(&g_P[2][off]);
        float4 v3 = *reinterpret_cast<const float4*>(&g_P[3][off]);
        float4 v4 = *reinterpret_cast<const float4*>(&g_P[4][off]);
        float4 v5 = *reinterpret_cast<const float4*>(&g_P[5][off]);
        float4 v6 = *reinterpret_cast<const float4*>(&g_P[6][off]);
        float4 v7 = *reinterpret_cast<const float4*>(&g_P[7][off]);
        float4 p;
        p.x = ((v0.x + v1.x) + (v2.x + v3.x)) + ((v4.x + v5.x) + (v6.x + v7.x));
        p.y = ((v0.y + v1.y) + (v2.y + v3.y)) + ((v4.y + v5.y) + (v6.y + v7.y));
        p.z = ((v0.z + v1.z) + (v2.z + v3.z)) + ((v4.z + v5.z) + (v6.z + v7.z));
        p.w = ((v0.w + v1.w) + (v2.w + v3.w)) + ((v4.w + v5.w) + (v6.w + v7.w));
        s_d[j0 + 0] = fmaxf(sqa + s_sq[j0 + 0] - 2.f * p.x, 0.f);
        s_d[j0 + 1] = fmaxf(sqa + s_sq[j0 + 1] - 2.f * p.y, 0.f);
        s_d[j0 + 2] = fmaxf(sqa + s_sq[j0 + 2] - 2.f * p.z, 0.f);
        s_d[j0 + 3] = fmaxf(sqa + s_sq[j0 + 3] - 2.f * p.w, 0.f);
    }
    __syncthreads();

    // ---- register copies: d[t] = s_d[t*32+lane] ----
    float d[16];
    int lb[16];
#pragma unroll
    for (int t = 0; t < 16; t++) {
        d[t] = s_d[t * 32 + lane];
        lb[t] = s_lab[t * 32 + lane];
    }

    // ---- block-wide min over negatives ----
    {
        float nm = INF_F;
#pragma unroll
        for (int t = 0; t < 16; t++)
            if (lb[t] != la) nm = fminf(nm, d[t]);
#pragma unroll
        for (int o = 16; o > 0; o >>= 1)
            nm = fminf(nm, __shfl_xor_sync(0xFFFFFFFFu, nm, o));
        if (lane == 0) s_nm[warp] = nm;
    }
    __syncthreads();
    if (tid == 0)
        s_nmin = fminf(fminf(s_nm[0], s_nm[1]), fminf(s_nm[2], s_nm[3]));
    __syncthreads();
    const float nmin = s_nmin;

    long long accll = 0, cntll = 0;
    if (nmin < 1e29f) {
        float sum = 0.f;
        int cnt = 0;
#pragma unroll 1
        for (int tt0 = 0; tt0 < 4; tt0++) {
            const int t = warp * 4 + tt0;
            const int j = t * 32 + lane;
            unsigned m = __ballot_sync(0xFFFFFFFFu, (j > a) && (lb[t] == la));
            while (m) {
                const int lp = __ffs(m) - 1;
                m &= m - 1;
                const float ap = __shfl_sync(0xFFFFFFFFu, d[t], lp);
                const float apM = ap + MARGIN;
                float smin = INF_F;
#pragma unroll
                for (int q = 0; q < 16; q++) {
                    bool semi = (lb[q] != la) && (d[q] > ap) && (d[q] < apM);
                    if (semi) smin = fminf(smin, d[q]);
                }
#pragma unroll
                for (int o = 16; o > 0; o >>= 1)
                    smin = fminf(smin, __shfl_xor_sync(0xFFFFFFFFu, smin, o));
                const float negd = (smin < 1e29f) ? smin : nmin;
                sum += fmaxf(ap - negd + MARGIN, 0.f);
                cnt++;
            }
        }
        if (lane == 0 && cnt) {
            accll = __double2ll_rn((double)sum * 4294967296.0);
            cntll = cnt;
        }
    }
    if (lane == 0 && (accll | cntll)) {
        atomicAdd(&g_ctl.acc, (ull)accll);
        atomicAdd(&g_ctl.cnt, (ull)cntll);
    }

    // ---- finalize ----
    __syncthreads();
    __threadfence();
    if (tid == 0) {
        const int o = atomicAdd(&g_ctl.done, 1);
        if (o == NB - 1) {
            __threadfence();
            ull av = *(volatile ull*)&g_ctl.acc;
            ull cv = *(volatile ull*)&g_ctl.cnt;
            out[0] = (float)(((double)av / 4294967296.0) / (double)(cv ? cv : 1ull));
        }
    }
}

extern "C" void kernel_launch(void* const* d_in, const int* in_sizes, int n_in,
                              void* d_out, int out_size) {
    const float* emb = (const float*)d_in[0];
    const int* labels = (const int*)d_in[1];
    float* out = (float*)d_out;

    dim3 grid(8, 4, NSPLIT);
    k_gemm<<<grid, 256>>>(emb);
    k_mine<<<NB, 128>>>(labels, out);
}